// round 13
// baseline (speedup 1.0000x reference)
#include <cuda_runtime.h>
#include <stdint.h>

// Problem constants (fixed by setup_inputs)
#define B_SZ     32
#define C_SZ     384
#define T_SZ     1024
#define MAXLEN   8192
#define CH_OUT   (C_SZ + 2)          // 386
#define MAX_DUR  10000

#define THREADS     256
#define POS_PER_TH  4
#define POS_CHUNK   (THREADS * POS_PER_TH)   // 1024
#define N_PCHUNK    (MAXLEN / POS_CHUNK)     // 8
#define CH_GRP      4
#define N_YGRP      (C_SZ / CH_GRP + 1)      // 96 full groups + 1 extras group

// ---------------------------------------------------------------------------
// Fused kernel: per-block duration scan (smem) + expand-gather.
// grid = (N_PCHUNK=8, N_YGRP=97, B=32), 256 threads, 4 positions/thread,
// 4 channels per block. No scratch globals, no prep kernel, no dependency
// bubble. tok derived in-block: 10-step binary search for pos0, then a
// 3-step walk (durations >= 1 ==> tok advances <= 1 per position).
// ---------------------------------------------------------------------------
__global__ __launch_bounds__(THREADS) void fused_kernel(
    const float* __restrict__ x,        // [B, C, T]
    const int*   __restrict__ duration, // [B, T] int32
    float* __restrict__ out,            // [B, CH_OUT, MAXLEN] (+ mel_len tail)
    long long out_size)
{
    const int b    = blockIdx.z;
    const int yg   = blockIdx.y;
    const int tid  = threadIdx.x;
    const int lane = tid & 31;
    const int wid  = tid >> 5;

    __shared__ int s_ends[T_SZ];
    __shared__ int wsum[8];

    // ---- per-block scan of this batch's 1024 durations (4/thread) ----
    int4 dl = reinterpret_cast<const int4*>(duration + b * T_SZ)[tid];
    int d0 = abs(dl.x); d0 = d0 < 1 ? 1 : (d0 > MAX_DUR ? MAX_DUR : d0);
    int d1 = abs(dl.y); d1 = d1 < 1 ? 1 : (d1 > MAX_DUR ? MAX_DUR : d1);
    int d2 = abs(dl.z); d2 = d2 < 1 ? 1 : (d2 > MAX_DUR ? MAX_DUR : d2);
    int d3 = abs(dl.w); d3 = d3 < 1 ? 1 : (d3 > MAX_DUR ? MAX_DUR : d3);

    int e0 = d0, e1 = e0 + d1, e2 = e1 + d2, e3 = e2 + d3;  // local inclusive

    // warp inclusive scan over per-thread sums (e3)
    int v = e3;
    #pragma unroll
    for (int off = 1; off < 32; off <<= 1) {
        int u = __shfl_up_sync(0xFFFFFFFFu, v, off);
        if (lane >= off) v += u;
    }
    if (lane == 31) wsum[wid] = v;
    __syncthreads();

    if (wid == 0) {
        int w = (lane < 8) ? wsum[lane] : 0;
        #pragma unroll
        for (int off = 1; off < 8; off <<= 1) {
            int u = __shfl_up_sync(0xFFFFFFFFu, w, off);
            if (lane >= off) w += u;
        }
        if (lane < 8) wsum[lane] = w;   // inclusive warp-sum scan
    }
    __syncthreads();

    const int base = ((wid > 0) ? wsum[wid - 1] : 0) + (v - e3);  // excl prefix
    const int sbase = tid << 2;
    s_ends[sbase + 0] = base + e0;
    s_ends[sbase + 1] = base + e1;
    s_ends[sbase + 2] = base + e2;
    s_ends[sbase + 3] = base + e3;
    __syncthreads();

    const int total = s_ends[T_SZ - 1];

    // mel_len: one writer per batch
    if (yg == 0 && blockIdx.x == 0 && tid == 0) {
        long long mbase = (long long)B_SZ * CH_OUT * MAXLEN;
        if (mbase + b < out_size)
            out[mbase + b] = (float)total;
    }

    // ---- tok for this thread's 4 positions ----
    const int pos0 = (blockIdx.x * THREADS + tid) * POS_PER_TH;

    int t0 = 0;
    #pragma unroll
    for (int step = T_SZ / 2; step > 0; step >>= 1)
        if (s_ends[t0 + step - 1] <= pos0) t0 += step;
    if (t0 > T_SZ - 1) t0 = T_SZ - 1;
    int t1 = t0 + ((t0 < T_SZ - 1) && (s_ends[t0] <= pos0 + 1) ? 1 : 0);
    int t2 = t1 + ((t1 < T_SZ - 1) && (s_ends[t1] <= pos0 + 2) ? 1 : 0);
    int t3 = t2 + ((t2 < T_SZ - 1) && (s_ends[t2] <= pos0 + 3) ? 1 : 0);

    const bool v0 = pos0 + 0 < total;
    const bool v1 = pos0 + 1 < total;
    const bool v2 = pos0 + 2 < total;
    const bool v3 = pos0 + 3 < total;

    float* const outb = out + (long long)b * CH_OUT * MAXLEN + pos0;

    if (yg < C_SZ / CH_GRP) {
        const int ch0 = yg * CH_GRP;
        const float* const xb = x + ((long long)b * C_SZ + ch0) * T_SZ;
        #pragma unroll
        for (int c = 0; c < CH_GRP; ++c) {
            const float* __restrict__ xrow = xb + c * T_SZ;
            float4 vv;
            vv.x = v0 ? __ldg(&xrow[t0]) : 0.0f;
            vv.y = v1 ? __ldg(&xrow[t1]) : 0.0f;
            vv.z = v2 ? __ldg(&xrow[t2]) : 0.0f;
            vv.w = v3 ? __ldg(&xrow[t3]) : 0.0f;
            __stcs(reinterpret_cast<float4*>(outb + (long long)(ch0 + c) * MAXLEN), vv);
        }
    } else {
        // ch 384 = idx_in (pos - start[tok]), ch 385 = length (d[tok])
        float4 iv = {0.f, 0.f, 0.f, 0.f};
        float4 lv = {0.f, 0.f, 0.f, 0.f};
        if (v0) {
            int en = s_ends[t0], st = (t0 ? s_ends[t0 - 1] : 0);
            iv.x = (float)(pos0 + 0 - st); lv.x = (float)(en - st);
        }
        if (v1) {
            int en = s_ends[t1], st = (t1 ? s_ends[t1 - 1] : 0);
            iv.y = (float)(pos0 + 1 - st); lv.y = (float)(en - st);
        }
        if (v2) {
            int en = s_ends[t2], st = (t2 ? s_ends[t2 - 1] : 0);
            iv.z = (float)(pos0 + 2 - st); lv.z = (float)(en - st);
        }
        if (v3) {
            int en = s_ends[t3], st = (t3 ? s_ends[t3 - 1] : 0);
            iv.w = (float)(pos0 + 3 - st); lv.w = (float)(en - st);
        }
        float* oi = outb + (long long)C_SZ * MAXLEN;
        __stcs(reinterpret_cast<float4*>(oi),          iv);
        __stcs(reinterpret_cast<float4*>(oi + MAXLEN), lv);
    }
}

// ---------------------------------------------------------------------------
extern "C" void kernel_launch(void* const* d_in, const int* in_sizes, int n_in,
                              void* d_out, int out_size)
{
    const float* x   = (const float*)d_in[0];
    const int*   dur = (const int*)d_in[1];
    float*       out = (float*)d_out;

    dim3 grid(N_PCHUNK, N_YGRP, B_SZ);
    fused_kernel<<<grid, THREADS>>>(x, dur, out, (long long)out_size);
}